// round 1
// baseline (speedup 1.0000x reference)
#include <cuda_runtime.h>
#include <cuda_bf16.h>

// Problem dims (fixed by the reference):
//   B=8, Cin=256, Cout=256, H=128, W=128
// Inputs (metadata order):
//   d_in[0] x            float [8][256][128][128]
//   d_in[1] delta_weight float [8][256][256][1][1]  -> [b][o][c]
//   d_in[2] dw_weight    float [256][1][3][3]       -> [c][3][3]
//   d_in[3] pw_weight    float [256][256][1][1]     -> [o][c]
// Output: float [8][256][128][128]

#define BB   8
#define CIN  256
#define COUT 256
#define HH   128
#define WW   128
#define CHUNK 8          // channels processed per shared-memory stage
#define OTILE 128        // Cout per CTA

// 2 MB scratch for transposed per-sample weights: wt[b][c][o]
__device__ float g_wt[BB * CIN * COUT];

// ---------------------------------------------------------------------------
// Pre-kernel: wt[b][c][o] = pw[o][c] + delta[b][o][c]
// ---------------------------------------------------------------------------
__global__ void build_wt_kernel(const float* __restrict__ delta,
                                const float* __restrict__ pw) {
    int idx = blockIdx.x * blockDim.x + threadIdx.x;   // [b][c][o]
    if (idx >= BB * CIN * COUT) return;
    int o = idx & 255;
    int c = (idx >> 8) & 255;
    int b = idx >> 16;
    g_wt[idx] = pw[o * CIN + c] + delta[b * (COUT * CIN) + o * CIN + c];
}

// ---------------------------------------------------------------------------
// Fused depthwise-3x3 + per-sample pointwise GEMM.
// Grid: (H, COUT/OTILE, B). Block: 256 threads.
// Each CTA produces out[b, o_base:o_base+128, h, 0:128].
// Thread t: px = (t&31)*4 .. +3 , o = o_base + (t>>5)*16 .. +15   (64 accums)
// ---------------------------------------------------------------------------
__global__ __launch_bounds__(256) void fused_sepconv_kernel(
    const float* __restrict__ x,
    const float* __restrict__ dwk,
    float* __restrict__ out) {

    const int h      = blockIdx.x;
    const int o_base = blockIdx.y * OTILE;
    const int b      = blockIdx.z;
    const int tid    = threadIdx.x;

    __shared__ float xs[CHUNK][3][132];       // +pad cols: idx 0 and 129 are zero
    __shared__ float dw_sh[CHUNK][WW];        // depthwise row result per channel
    __shared__ float w_sh[CHUNK][OTILE];      // wt[b][c][o_base..]
    __shared__ float k_sh[CIN * 9];           // all depthwise taps

    for (int i = tid; i < CIN * 9; i += 256) k_sh[i] = dwk[i];

    const int px0 = (tid & 31) * 4;
    const int ot  = (tid >> 5) * 16;

    float4 acc[16];
    #pragma unroll
    for (int j = 0; j < 16; j++) acc[j] = make_float4(0.f, 0.f, 0.f, 0.f);

    for (int c0 = 0; c0 < CIN; c0 += CHUNK) {
        __syncthreads();   // previous chunk's readers of xs/dw_sh/w_sh are done

        // ---- stage 1: load x rows (h-1,h,h+1) for CHUNK channels + weights
        #pragma unroll
        for (int it = 0; it < (CHUNK * 3 * WW) / 256; it++) {
            int i   = tid + it * 256;
            int cc  = i / (3 * WW);
            int rem = i - cc * (3 * WW);
            int r   = rem >> 7;
            int col = rem & 127;
            int hh  = h - 1 + r;
            float v = 0.f;
            if (hh >= 0 && hh < HH)
                v = x[(((b * CIN) + c0 + cc) * HH + hh) * WW + col];
            xs[cc][r][col + 1] = v;
        }
        if (tid < CHUNK * 3) {
            int cc = tid / 3, r = tid - cc * 3;
            xs[cc][r][0]   = 0.f;
            xs[cc][r][129] = 0.f;
        }
        #pragma unroll
        for (int it = 0; it < (CHUNK * OTILE) / 256; it++) {
            int i  = tid + it * 256;
            int cc = i >> 7;           // OTILE==128
            int o  = i & 127;
            w_sh[cc][o] = g_wt[(((b * CIN) + c0 + cc) << 8) + o_base + o];
        }
        __syncthreads();

        // ---- stage 2: depthwise 3x3 for this chunk (4 outputs per thread)
        #pragma unroll
        for (int k = 0; k < 4; k++) {
            int i   = tid + k * 256;
            int cc  = i >> 7;
            int col = i & 127;
            const float* kk = &k_sh[(c0 + cc) * 9];
            float s = 0.f;
            #pragma unroll
            for (int r = 0; r < 3; r++)
                #pragma unroll
                for (int dc = 0; dc < 3; dc++)
                    s += xs[cc][r][col + dc] * kk[r * 3 + dc];
            dw_sh[cc][col] = s;
        }
        __syncthreads();

        // ---- stage 3: rank-1 updates (64 FMA per thread per channel)
        #pragma unroll 2
        for (int cc = 0; cc < CHUNK; cc++) {
            const float4 d = *(const float4*)(&dw_sh[cc][px0]);
            #pragma unroll
            for (int jq = 0; jq < 4; jq++) {
                const float4 wv = *(const float4*)(&w_sh[cc][ot + jq * 4]);
                float4* a0 = &acc[jq * 4 + 0];
                float4* a1 = &acc[jq * 4 + 1];
                float4* a2 = &acc[jq * 4 + 2];
                float4* a3 = &acc[jq * 4 + 3];
                a0->x += wv.x * d.x; a0->y += wv.x * d.y; a0->z += wv.x * d.z; a0->w += wv.x * d.w;
                a1->x += wv.y * d.x; a1->y += wv.y * d.y; a1->z += wv.y * d.z; a1->w += wv.y * d.w;
                a2->x += wv.z * d.x; a2->y += wv.z * d.y; a2->z += wv.z * d.z; a2->w += wv.z * d.w;
                a3->x += wv.w * d.x; a3->y += wv.w * d.y; a3->z += wv.w * d.z; a3->w += wv.w * d.w;
            }
        }
    }

    // ---- epilogue: 16 float4 stores, coalesced across the 32 px-threads
    #pragma unroll
    for (int j = 0; j < 16; j++) {
        int o = o_base + ot + j;
        *(float4*)(&out[(((b * COUT) + o) * HH + h) * WW + px0]) = acc[j];
    }
}

// ---------------------------------------------------------------------------
extern "C" void kernel_launch(void* const* d_in, const int* in_sizes, int n_in,
                              void* d_out, int out_size) {
    const float* x     = (const float*)d_in[0];
    const float* delta = (const float*)d_in[1];
    const float* dwk   = (const float*)d_in[2];
    const float* pw    = (const float*)d_in[3];
    float* out = (float*)d_out;

    build_wt_kernel<<<(BB * CIN * COUT + 255) / 256, 256>>>(delta, pw);

    dim3 grid(HH, COUT / OTILE, BB);
    fused_sepconv_kernel<<<grid, 256>>>(x, dwk, out);
}

// round 4
// speedup vs baseline: 2.9898x; 2.9898x over previous
#include <cuda_runtime.h>
#include <cuda_bf16.h>
#include <cstdint>

#define BB   8
#define CIN  256
#define COUT 256
#define HH   128
#define WW   128
#define CK   64                // channels per chunk
#define NCHUNK (CIN/CK)        // 4
#define NT   512               // threads per CTA (16 warps)

// precomputed per-sample pointwise weights, bf16 hi/lo split: [b][o][c]
__device__ __align__(16) __nv_bfloat16 g_whi[BB*COUT*CIN];
__device__ __align__(16) __nv_bfloat16 g_wlo[BB*COUT*CIN];

// ---------------- SMEM layout (bytes) ----------------
static constexpr int S_DWK = 0;                    // 256*9 floats = 9216
static constexpr int S_AHI = 9216;                 // [256 o][64 c] bf16 = 32768 (swizzled)
static constexpr int S_ALO = S_AHI + 32768;        // 32768
static constexpr int S_BHI = S_ALO + 32768;        // [64 c][128 px] bf16 = 16384 (swizzled)
static constexpr int S_BLO = S_BHI + 16384;        // 16384
static constexpr int S_TOTAL = S_BLO + 16384;      // 107520

__device__ __forceinline__ uint32_t smem_u32(const void* p){
    uint32_t a;
    asm("{ .reg .u64 t; cvta.to.shared.u64 t, %1; cvt.u32.u64 %0, t; }" : "=r"(a) : "l"(p));
    return a;
}

__device__ __forceinline__ void ldsm_x4(uint32_t* r, uint32_t addr){
    asm volatile("ldmatrix.sync.aligned.m8n8.x4.shared.b16 {%0,%1,%2,%3}, [%4];"
        : "=r"(r[0]), "=r"(r[1]), "=r"(r[2]), "=r"(r[3]) : "r"(addr));
}
__device__ __forceinline__ void ldsm_x4_t(uint32_t* r, uint32_t addr){
    asm volatile("ldmatrix.sync.aligned.m8n8.x4.trans.shared.b16 {%0,%1,%2,%3}, [%4];"
        : "=r"(r[0]), "=r"(r[1]), "=r"(r[2]), "=r"(r[3]) : "r"(addr));
}
__device__ __forceinline__ void mma16816(float* c, const uint32_t* a,
                                         uint32_t b0, uint32_t b1){
    asm volatile("mma.sync.aligned.m16n8k16.row.col.f32.bf16.bf16.f32 "
        "{%0,%1,%2,%3}, {%4,%5,%6,%7}, {%8,%9}, {%0,%1,%2,%3};"
        : "+f"(c[0]), "+f"(c[1]), "+f"(c[2]), "+f"(c[3])
        : "r"(a[0]), "r"(a[1]), "r"(a[2]), "r"(a[3]), "r"(b0), "r"(b1));
}

// ---------------- pre-kernel: build bf16 hi/lo of per-sample weights --------
__global__ void build_w_kernel(const float* __restrict__ delta,
                               const float* __restrict__ pw){
    int i = blockIdx.x * 256 + threadIdx.x;            // [b][o][c]
    if (i >= BB*COUT*CIN) return;
    int c = i & 255, o = (i >> 8) & 255;
    float w = pw[o*CIN + c] + delta[i];
    __nv_bfloat16 hv = __float2bfloat16(w);
    g_whi[i] = hv;
    g_wlo[i] = __float2bfloat16(w - __bfloat162float(hv));
}

// ---------------- fused depthwise 3x3 + per-sample GEMM via mma.sync --------
// grid (HH, BB); 512 threads. CTA computes out[b, 0:256, h, 0:128].
// Warp w: o rows [ (w&7)*32, +32 ), px cols [ (w>>3)*64, +64 ).
__global__ __launch_bounds__(NT, 1)
void fused_mma_kernel(const float* __restrict__ x,
                      const float* __restrict__ dwk,
                      float* __restrict__ out){
    extern __shared__ char smem[];
    const uint32_t sb = smem_u32(smem);
    const int tid = threadIdx.x;
    const int wid = tid >> 5, lid = tid & 31;
    const int h = blockIdx.x, b = blockIdx.y;

    for (int i = tid; i < CIN*9; i += NT)
        ((float*)(smem + S_DWK))[i] = dwk[i];

    const int m_base = (wid & 7) * 32;
    const int n_base = (wid >> 3) * 64;
    const uint32_t lmask = (uint32_t)(lid & 7) << 4;   // swizzle xor for this lane

    float acc[2][8][4];
    #pragma unroll
    for (int mt = 0; mt < 2; ++mt)
        #pragma unroll
        for (int j = 0; j < 8; ++j)
            #pragma unroll
            for (int q = 0; q < 4; ++q) acc[mt][j][q] = 0.f;

    for (int ch = 0; ch < NCHUNK; ++ch){
        __syncthreads();   // previous chunk's ldmatrix readers done

        // ---- stage A: weights hi/lo -> SMEM, 16B chunks, xor-swizzled rows
        {
            const uint4* ghi = (const uint4*)g_whi;
            const uint4* glo = (const uint4*)g_wlo;
            #pragma unroll
            for (int it = 0; it < 4; ++it){
                int i   = tid + it*NT;                // 0..2047
                int o   = i >> 3, ck16 = i & 7;       // 8 x 16B per o-row
                uint32_t byte = (uint32_t)(o*128 + ck16*16);
                uint32_t sw   = byte ^ ((uint32_t)(o & 7) << 4);
                int gi = (b*COUT + o)*32 + ch*8 + ck16;
                *(uint4*)(smem + S_AHI + sw) = ghi[gi];
                *(uint4*)(smem + S_ALO + sw) = glo[gi];
            }
        }

        // ---- stage B: depthwise 3x3 -> bf16 split -> SMEM [c][px] swizzled
        #pragma unroll
        for (int it = 0; it < 4; ++it){
            int cl = wid + it*16;                     // 0..63
            int c  = ch*CK + cl;
            const float* kk = (const float*)(smem + S_DWK) + c*9;
            float s0=0.f, s1=0.f, s2=0.f, s3=0.f;
            const float* xrow = x + (size_t)((b*CIN + c)*HH)*WW + lid*4;
            #pragma unroll
            for (int r = 0; r < 3; ++r){
                int hh2 = h - 1 + r;
                float4 f = make_float4(0.f,0.f,0.f,0.f);
                if (hh2 >= 0 && hh2 < HH) f = *(const float4*)(xrow + hh2*WW);
                float lf = __shfl_up_sync(0xffffffffu, f.w, 1);
                float rt = __shfl_down_sync(0xffffffffu, f.x, 1);
                if (lid == 0)  lf = 0.f;
                if (lid == 31) rt = 0.f;
                float ka = kk[r*3+0], kb = kk[r*3+1], kc = kk[r*3+2];
                s0 += ka*lf  + kb*f.x + kc*f.y;
                s1 += ka*f.x + kb*f.y + kc*f.z;
                s2 += ka*f.y + kb*f.z + kc*f.w;
                s3 += ka*f.z + kb*f.w + kc*rt;
            }
            __nv_bfloat16 h0 = __float2bfloat16(s0), h1 = __float2bfloat16(s1);
            __nv_bfloat16 h2 = __float2bfloat16(s2), h3 = __float2bfloat16(s3);
            __nv_bfloat16 l0 = __float2bfloat16(s0 - __bfloat162float(h0));
            __nv_bfloat16 l1 = __float2bfloat16(s1 - __bfloat162float(h1));
            __nv_bfloat16 l2 = __float2bfloat16(s2 - __bfloat162float(h2));
            __nv_bfloat16 l3 = __float2bfloat16(s3 - __bfloat162float(h3));
            __nv_bfloat162 hp0; hp0.x = h0; hp0.y = h1;
            __nv_bfloat162 hp1; hp1.x = h2; hp1.y = h3;
            __nv_bfloat162 lp0; lp0.x = l0; lp0.y = l1;
            __nv_bfloat162 lp1; lp1.x = l2; lp1.y = l3;
            uint32_t byte = (uint32_t)(cl*256 + lid*8);
            uint32_t sw   = byte ^ ((uint32_t)(cl & 7) << 4);
            *(uint2*)(smem + S_BHI + sw) = make_uint2(*(uint32_t*)&hp0, *(uint32_t*)&hp1);
            *(uint2*)(smem + S_BLO + sw) = make_uint2(*(uint32_t*)&lp0, *(uint32_t*)&lp1);
        }
        __syncthreads();

        // ---- mma: 3 split terms x 4 k16-steps, warp tile 32x64
        #pragma unroll
        for (int term = 0; term < 3; ++term){
            const uint32_t abase = sb + ((term == 1) ? S_ALO : S_AHI);
            const uint32_t bbase = sb + ((term == 2) ? S_BLO : S_BHI);
            #pragma unroll
            for (int ks = 0; ks < 4; ++ks){
                uint32_t ar[2][4];
                #pragma unroll
                for (int mt = 0; mt < 2; ++mt){
                    int row = m_base + mt*16 + (lid & 15);
                    uint32_t col = ((uint32_t)(ks*32 + (lid >> 4)*16)) ^ lmask;
                    ldsm_x4(ar[mt], abase + (uint32_t)row*128 + col);
                }
                uint32_t br[4][4];
                #pragma unroll
                for (int nt = 0; nt < 4; ++nt){
                    int krow = ks*16 + (lid & 15);
                    uint32_t col = ((uint32_t)(nt*32 + (lid >> 4)*16)) ^ lmask;
                    ldsm_x4_t(br[nt], bbase + (uint32_t)krow*256
                                      + (uint32_t)(n_base*2) + col);
                }
                #pragma unroll
                for (int mt = 0; mt < 2; ++mt)
                    #pragma unroll
                    for (int j = 0; j < 8; ++j)
                        mma16816(acc[mt][j], ar[mt],
                                 br[j>>1][(j&1)*2], br[j>>1][(j&1)*2 + 1]);
            }
        }
    }

    // ---- epilogue: register accumulators -> gmem (float2 stores)
    // C fragment: c0,c1 at (o, px), c2,c3 at (o+8, px). One o step = HH*WW floats.
    #pragma unroll
    for (int mt = 0; mt < 2; ++mt){
        #pragma unroll
        for (int j = 0; j < 8; ++j){
            int o  = m_base + mt*16 + (lid >> 2);
            int px = n_base + j*8 + (lid & 3)*2;
            float* p = out + ((size_t)(b*COUT + o)*HH + h)*WW + px;
            *(float2*)p = make_float2(acc[mt][j][0], acc[mt][j][1]);
            *(float2*)(p + (size_t)8*HH*WW) = make_float2(acc[mt][j][2], acc[mt][j][3]);
        }
    }
}

// ---------------------------------------------------------------------------
extern "C" void kernel_launch(void* const* d_in, const int* in_sizes, int n_in,
                              void* d_out, int out_size){
    const float* x     = (const float*)d_in[0];
    const float* delta = (const float*)d_in[1];
    const float* dwk   = (const float*)d_in[2];
    const float* pw    = (const float*)d_in[3];
    float* out = (float*)d_out;

    cudaFuncSetAttribute(fused_mma_kernel,
                         cudaFuncAttributeMaxDynamicSharedMemorySize, S_TOTAL);

    build_w_kernel<<<(BB*COUT*CIN + 255)/256, 256>>>(delta, pw);
    fused_mma_kernel<<<dim3(HH, BB), NT, S_TOTAL>>>(x, dwk, out);
}

// round 5
// speedup vs baseline: 3.6678x; 1.2268x over previous
#include <cuda_runtime.h>
#include <cuda_bf16.h>
#include <cstdint>

#define BB   8
#define CIN  256
#define COUT 256
#define HH   128
#define WW   128
#define CK   64                // channels per chunk
#define NCHUNK (CIN/CK)        // 4
#define NT   256               // threads per CTA (8 warps)

// precomputed per-sample pointwise weights, bf16 hi/lo split: [b][o][c]
__device__ __align__(16) __nv_bfloat16 g_whi[BB*COUT*CIN];
__device__ __align__(16) __nv_bfloat16 g_wlo[BB*COUT*CIN];

// ---------------- SMEM layout (bytes) ----------------
static constexpr int S_DWK = 0;                    // 256*9 floats = 9216
static constexpr int S_AHI = 9216;                 // [128 o][64 c] bf16 = 16384 (swizzled)
static constexpr int S_ALO = S_AHI + 16384;        // 16384
static constexpr int S_BHI = S_ALO + 16384;        // [64 c][128 px] bf16 = 16384 (swizzled)
static constexpr int S_BLO = S_BHI + 16384;        // 16384
static constexpr int S_TOTAL = S_BLO + 16384;      // 74752

__device__ __forceinline__ uint32_t smem_u32(const void* p){
    uint32_t a;
    asm("{ .reg .u64 t; cvta.to.shared.u64 t, %1; cvt.u32.u64 %0, t; }" : "=r"(a) : "l"(p));
    return a;
}
__device__ __forceinline__ void cp_async16(uint32_t saddr, const void* g){
    asm volatile("cp.async.ca.shared.global [%0], [%1], 16;" :: "r"(saddr), "l"(g));
}
#define CP_COMMIT() asm volatile("cp.async.commit_group;" ::: "memory")
#define CP_WAIT0()  asm volatile("cp.async.wait_group 0;" ::: "memory")

__device__ __forceinline__ void ldsm_x4(uint32_t* r, uint32_t addr){
    asm volatile("ldmatrix.sync.aligned.m8n8.x4.shared.b16 {%0,%1,%2,%3}, [%4];"
        : "=r"(r[0]), "=r"(r[1]), "=r"(r[2]), "=r"(r[3]) : "r"(addr));
}
__device__ __forceinline__ void ldsm_x4_t(uint32_t* r, uint32_t addr){
    asm volatile("ldmatrix.sync.aligned.m8n8.x4.trans.shared.b16 {%0,%1,%2,%3}, [%4];"
        : "=r"(r[0]), "=r"(r[1]), "=r"(r[2]), "=r"(r[3]) : "r"(addr));
}
__device__ __forceinline__ void mma16816(float* c, const uint32_t* a,
                                         uint32_t b0, uint32_t b1){
    asm volatile("mma.sync.aligned.m16n8k16.row.col.f32.bf16.bf16.f32 "
        "{%0,%1,%2,%3}, {%4,%5,%6,%7}, {%8,%9}, {%0,%1,%2,%3};"
        : "+f"(c[0]), "+f"(c[1]), "+f"(c[2]), "+f"(c[3])
        : "r"(a[0]), "r"(a[1]), "r"(a[2]), "r"(a[3]), "r"(b0), "r"(b1));
}

// ---------------- pre-kernel: build bf16 hi/lo of per-sample weights --------
__global__ void build_w_kernel(const float* __restrict__ delta,
                               const float* __restrict__ pw){
    int i = blockIdx.x * 256 + threadIdx.x;            // [b][o][c]
    if (i >= BB*COUT*CIN) return;
    int c = i & 255, o = (i >> 8) & 255;
    float w = pw[o*CIN + c] + delta[i];
    __nv_bfloat16 hv = __float2bfloat16(w);
    g_whi[i] = hv;
    g_wlo[i] = __float2bfloat16(w - __bfloat162float(hv));
}

// ---------------- fused depthwise 3x3 + per-sample GEMM via mma.sync --------
// grid (HH, 2, BB); 256 threads (8 warps). CTA computes
// out[b, half*128 : half*128+128, h, 0:128].
// Warp w: o rows [ (w&3)*32, +32 ), px cols [ (w>>2)*64, +64 ).
__global__ __launch_bounds__(NT, 2)
void fused_mma_kernel(const float* __restrict__ x,
                      const float* __restrict__ dwk,
                      float* __restrict__ out){
    extern __shared__ char smem[];
    const uint32_t sb = smem_u32(smem);
    const int tid = threadIdx.x;
    const int wid = tid >> 5, lid = tid & 31;
    const int h = blockIdx.x, half = blockIdx.y, b = blockIdx.z;

    for (int i = tid; i < CIN*9; i += NT)
        ((float*)(smem + S_DWK))[i] = dwk[i];

    const int m_base = (wid & 3) * 32;
    const int n_base = (wid >> 2) * 64;
    const uint32_t lmask = (uint32_t)(lid & 7) << 4;   // swizzle xor for this lane

    float acc[2][8][4];
    #pragma unroll
    for (int mt = 0; mt < 2; ++mt)
        #pragma unroll
        for (int j = 0; j < 8; ++j)
            #pragma unroll
            for (int q = 0; q < 4; ++q) acc[mt][j][q] = 0.f;

    for (int ch = 0; ch < NCHUNK; ++ch){
        __syncthreads();   // previous chunk's ldmatrix readers done

        // ---- stage A: weights hi/lo -> SMEM via cp.async (overlaps depthwise)
        {
            const uint4* ghi = (const uint4*)g_whi;
            const uint4* glo = (const uint4*)g_wlo;
            #pragma unroll
            for (int it = 0; it < 4; ++it){
                int i   = tid + it*NT;                // 0..1023
                int o   = i >> 3, ck16 = i & 7;       // 8 x 16B per o-row
                uint32_t byte = (uint32_t)(o*128 + ck16*16);
                uint32_t sw   = byte ^ ((uint32_t)(o & 7) << 4);
                int gi = (b*COUT + half*128 + o)*32 + ch*8 + ck16;
                cp_async16(sb + S_AHI + sw, ghi + gi);
                cp_async16(sb + S_ALO + sw, glo + gi);
            }
            CP_COMMIT();
        }

        // ---- stage B: depthwise 3x3 -> bf16 split -> SMEM [c][px] swizzled
        #pragma unroll
        for (int it = 0; it < 8; ++it){
            int cl = wid + it*8;                      // 0..63
            int c  = ch*CK + cl;
            const float* kk = (const float*)(smem + S_DWK) + c*9;
            float s0=0.f, s1=0.f, s2=0.f, s3=0.f;
            const float* xrow = x + (size_t)((b*CIN + c)*HH)*WW + lid*4;
            #pragma unroll
            for (int r = 0; r < 3; ++r){
                int hh2 = h - 1 + r;
                float4 f = make_float4(0.f,0.f,0.f,0.f);
                if (hh2 >= 0 && hh2 < HH) f = *(const float4*)(xrow + hh2*WW);
                float lf = __shfl_up_sync(0xffffffffu, f.w, 1);
                float rt = __shfl_down_sync(0xffffffffu, f.x, 1);
                if (lid == 0)  lf = 0.f;
                if (lid == 31) rt = 0.f;
                float ka = kk[r*3+0], kb = kk[r*3+1], kc = kk[r*3+2];
                s0 += ka*lf  + kb*f.x + kc*f.y;
                s1 += ka*f.x + kb*f.y + kc*f.z;
                s2 += ka*f.y + kb*f.z + kc*f.w;
                s3 += ka*f.z + kb*f.w + kc*rt;
            }
            __nv_bfloat16 h0 = __float2bfloat16(s0), h1 = __float2bfloat16(s1);
            __nv_bfloat16 h2 = __float2bfloat16(s2), h3 = __float2bfloat16(s3);
            __nv_bfloat16 l0 = __float2bfloat16(s0 - __bfloat162float(h0));
            __nv_bfloat16 l1 = __float2bfloat16(s1 - __bfloat162float(h1));
            __nv_bfloat16 l2 = __float2bfloat16(s2 - __bfloat162float(h2));
            __nv_bfloat16 l3 = __float2bfloat16(s3 - __bfloat162float(h3));
            __nv_bfloat162 hp0; hp0.x = h0; hp0.y = h1;
            __nv_bfloat162 hp1; hp1.x = h2; hp1.y = h3;
            __nv_bfloat162 lp0; lp0.x = l0; lp0.y = l1;
            __nv_bfloat162 lp1; lp1.x = l2; lp1.y = l3;
            uint32_t byte = (uint32_t)(cl*256 + lid*8);
            uint32_t sw   = byte ^ ((uint32_t)(cl & 7) << 4);
            *(uint2*)(smem + S_BHI + sw) = make_uint2(*(uint32_t*)&hp0, *(uint32_t*)&hp1);
            *(uint2*)(smem + S_BLO + sw) = make_uint2(*(uint32_t*)&lp0, *(uint32_t*)&lp1);
        }
        CP_WAIT0();
        __syncthreads();

        // ---- mma: term order hi*hi, lo*hi (reuse B frags), hi*lo
        #pragma unroll
        for (int ks = 0; ks < 4; ++ks){
            uint32_t ar[2][4];
            uint32_t br[4][4];
            #pragma unroll
            for (int term = 0; term < 3; ++term){
                const uint32_t abase = sb + ((term == 1) ? S_ALO : S_AHI);
                #pragma unroll
                for (int mt = 0; mt < 2; ++mt){
                    int row = m_base + mt*16 + (lid & 15);
                    uint32_t col = ((uint32_t)(ks*32 + (lid >> 4)*16)) ^ lmask;
                    ldsm_x4(ar[mt], abase + (uint32_t)row*128 + col);
                }
                if (term != 1){   // term 1 reuses term 0's B (both BHI)
                    const uint32_t bbase = sb + ((term == 2) ? S_BLO : S_BHI);
                    #pragma unroll
                    for (int nt = 0; nt < 4; ++nt){
                        int krow = ks*16 + (lid & 15);
                        uint32_t col = ((uint32_t)(nt*32 + (lid >> 4)*16)) ^ lmask;
                        ldsm_x4_t(br[nt], bbase + (uint32_t)krow*256
                                          + (uint32_t)(n_base*2) + col);
                    }
                }
                #pragma unroll
                for (int mt = 0; mt < 2; ++mt)
                    #pragma unroll
                    for (int j = 0; j < 8; ++j)
                        mma16816(acc[mt][j], ar[mt],
                                 br[j>>1][(j&1)*2], br[j>>1][(j&1)*2 + 1]);
            }
        }
    }

    // ---- epilogue: register accumulators -> gmem (float2 stores)
    // C fragment: c0,c1 at (o, px), c2,c3 at (o+8, px). One o step = HH*WW floats.
    #pragma unroll
    for (int mt = 0; mt < 2; ++mt){
        #pragma unroll
        for (int j = 0; j < 8; ++j){
            int o  = half*128 + m_base + mt*16 + (lid >> 2);
            int px = n_base + j*8 + (lid & 3)*2;
            float* p = out + ((size_t)(b*COUT + o)*HH + h)*WW + px;
            *(float2*)p = make_float2(acc[mt][j][0], acc[mt][j][1]);
            *(float2*)(p + (size_t)8*HH*WW) = make_float2(acc[mt][j][2], acc[mt][j][3]);
        }
    }
}

// ---------------------------------------------------------------------------
extern "C" void kernel_launch(void* const* d_in, const int* in_sizes, int n_in,
                              void* d_out, int out_size){
    const float* x     = (const float*)d_in[0];
    const float* delta = (const float*)d_in[1];
    const float* dwk   = (const float*)d_in[2];
    const float* pw    = (const float*)d_in[3];
    float* out = (float*)d_out;

    cudaFuncSetAttribute(fused_mma_kernel,
                         cudaFuncAttributeMaxDynamicSharedMemorySize, S_TOTAL);

    build_w_kernel<<<(BB*COUT*CIN + 255)/256, 256>>>(delta, pw);
    fused_mma_kernel<<<dim3(HH, 2, BB), NT, S_TOTAL>>>(x, dwk, out);
}